// round 1
// baseline (speedup 1.0000x reference)
#include <cuda_runtime.h>
#include <cuda_bf16.h>

// Problem constants
#define BB 64
#define SS 2048
#define HH 512
#define H4 128   // H in float4 units

// Scratch (module-scope device globals: allowed; no runtime allocation)
__device__ float4 g_P[SS * H4];    // pos_table @ W[0:512]     (4 MB)
__device__ float4 g_N[16 * H4];    // nest_table @ W[512:1024] (32 KB)
__device__ float4 g_G[8 * H4];     // seg_table @ W[1024:1536] (16 KB)
__device__ unsigned char g_combo[BB * SS];  // (nest<<3)|seg per token

// ---------------------------------------------------------------------------
// Kernel 1: per-row syntax scan. 64 blocks (one per batch row) x 128 threads.
// Each thread handles 16 consecutive tokens. Lindley recursion via
// (delta-sum, min-prefix-sum) segment aggregates, which compose associatively.
// ---------------------------------------------------------------------------
__global__ void scan_kernel(const int* __restrict__ tok) {
    __shared__ int sh_tok[SS];
    __shared__ int agg_sum[128];
    __shared__ int agg_min[128];
    __shared__ int agg_cnt[128];

    const int b = blockIdx.x;
    const int* t = tok + b * SS;
    for (int i = threadIdx.x; i < SS; i += 128) sh_tok[i] = t[i];
    __syncthreads();

    const int j = threadIdx.x;
    const int base = j * 16;

    // local aggregates
    int s = 0, mn = 0, cnt = 0;
#pragma unroll
    for (int e = 0; e < 16; e++) {
        int tk = sh_tok[base + e];
        int op = (tk == 40) | (tk == 123) | (tk == 91);
        int cl = (tk == 41) | (tk == 125) | (tk == 93);
        s += op - cl;
        mn = min(mn, s);
        cnt += (tk > 39990);
    }
    agg_sum[j] = s; agg_min[j] = mn; agg_cnt[j] = cnt;
    __syncthreads();

    // exclusive serial prefix over 128 thread aggregates (tiny kernel, fine)
    int S_pre = 0, M_pre = 0, C_pre = 0;   // M_pre starts at 0 => min(run_min, 0)
    for (int k = 0; k < j; k++) {
        M_pre = min(M_pre, S_pre + agg_min[k]);
        S_pre += agg_sum[k];
        C_pre += agg_cnt[k];
    }

    // replay with carry-in; level_i = s_i - min(0, cummin s_i), clipped to 15
    s = S_pre; mn = M_pre; cnt = C_pre;
    unsigned char* out = g_combo + b * SS + base;
#pragma unroll
    for (int e = 0; e < 16; e++) {
        int tk = sh_tok[base + e];
        int op = (tk == 40) | (tk == 123) | (tk == 91);
        int cl = (tk == 41) | (tk == 125) | (tk == 93);
        s += op - cl;
        mn = min(mn, s);
        cnt += (tk > 39990);
        int lvl = min(s - mn, 15);     // >= 0 automatically
        int seg = cnt & 7;
        out[e] = (unsigned char)((lvl << 3) | seg);
    }
}

// ---------------------------------------------------------------------------
// Kernel 2: FP32 SIMT GEMM  C[M,512] = A[M,512] @ B[512,512]
// 64x64 block tile, BK=32, 256 threads, 4x4 per-thread microtile.
// which: 0 -> g_P, 1 -> g_N, 2 -> g_G
// ---------------------------------------------------------------------------
__global__ void __launch_bounds__(256, 2)
gemm_k512(const float* __restrict__ A, const float* __restrict__ B,
          int M, int which) {
    __shared__ float As[32][64];   // transposed: As[k][m]
    __shared__ float Bs[32][64];   // Bs[k][n]

    float* C = (which == 0) ? (float*)g_P : (which == 1) ? (float*)g_N : (float*)g_G;

    const int tid = threadIdx.x;
    const int tx = tid & 15;       // n direction
    const int ty = tid >> 4;       // m direction
    const int m0 = blockIdx.x * 64;
    const int n0 = blockIdx.y * 64;

    float acc[4][4] = {};

    for (int k0 = 0; k0 < 512; k0 += 32) {
        // A tile: 64 rows x 32 cols = 512 float4, 2 per thread, transpose into As
#pragma unroll
        for (int l = 0; l < 2; l++) {
            int q = tid + l * 256;
            int r = q >> 3;        // 0..63
            int c4 = q & 7;        // 0..7
            float4 v = make_float4(0.f, 0.f, 0.f, 0.f);
            if (m0 + r < M)
                v = *(const float4*)(A + (size_t)(m0 + r) * 512 + k0 + c4 * 4);
            As[c4 * 4 + 0][r] = v.x;
            As[c4 * 4 + 1][r] = v.y;
            As[c4 * 4 + 2][r] = v.z;
            As[c4 * 4 + 3][r] = v.w;
        }
        // B tile: 32 rows x 64 cols = 512 float4, 2 per thread, direct layout
#pragma unroll
        for (int l = 0; l < 2; l++) {
            int q = tid + l * 256;
            int kr = q >> 4;       // 0..31
            int c4 = q & 15;       // 0..15
            *(float4*)(&Bs[kr][c4 * 4]) =
                *(const float4*)(B + (size_t)(k0 + kr) * 512 + n0 + c4 * 4);
        }
        __syncthreads();

#pragma unroll
        for (int k = 0; k < 32; k++) {
            float4 a = *(float4*)(&As[k][ty * 4]);
            float4 bv = *(float4*)(&Bs[k][tx * 4]);
            float av[4] = {a.x, a.y, a.z, a.w};
            float bw[4] = {bv.x, bv.y, bv.z, bv.w};
#pragma unroll
            for (int i = 0; i < 4; i++)
#pragma unroll
                for (int jj = 0; jj < 4; jj++)
                    acc[i][jj] += av[i] * bw[jj];
        }
        __syncthreads();
    }

#pragma unroll
    for (int i = 0; i < 4; i++) {
        int m = m0 + ty * 4 + i;
        if (m < M)
            *(float4*)(C + (size_t)m * 512 + n0 + tx * 4) =
                make_float4(acc[i][0], acc[i][1], acc[i][2], acc[i][3]);
    }
}

// ---------------------------------------------------------------------------
// Kernel 3: combine.  out[b,s,h] = P[s,h] + N[nest,h] + G[seg,h]
// Each thread owns one (s, h4) and loops over 8 batches -> P read from L2
// only 8x total instead of 64x; DRAM-write-bound.
// ---------------------------------------------------------------------------
__global__ void __launch_bounds__(256)
combine_kernel(float4* __restrict__ out) {
    unsigned int j = blockIdx.x * 256u + threadIdx.x;   // [0, 2^21)
    const int h4 = j & 127;
    const int s = (j >> 7) & 2047;
    const int bo = j >> 18;                              // 0..7

    const float4 p = g_P[s * H4 + h4];
#pragma unroll
    for (int bb = 0; bb < 8; bb++) {
        const int b = bo * 8 + bb;
        const unsigned char c = g_combo[b * SS + s];
        const float4 n = g_N[(c >> 3) * H4 + h4];
        const float4 g = g_G[(c & 7) * H4 + h4];
        float4 o;
        o.x = p.x + n.x + g.x;
        o.y = p.y + n.y + g.y;
        o.z = p.z + n.z + g.z;
        o.w = p.w + n.w + g.w;
        out[(((unsigned)b * SS + s) << 7) + h4] = o;
    }
}

// ---------------------------------------------------------------------------
extern "C" void kernel_launch(void* const* d_in, const int* in_sizes, int n_in,
                              void* d_out, int out_size) {
    const int*   tok  = (const int*)d_in[0];    // token_ids [64,2048] int32
    const float* pos  = (const float*)d_in[1];  // pos_table [2048,512]
    const float* nest = (const float*)d_in[2];  // nest_table [16,512]
    const float* seg  = (const float*)d_in[3];  // seg_table [8,512]
    const float* W    = (const float*)d_in[4];  // W [1536,512]
    float4* out = (float4*)d_out;               // [64,2048,512] f32

    scan_kernel<<<BB, 128>>>(tok);

    gemm_k512<<<dim3(SS / 64, 8), 256>>>(pos,  W,              SS, 0);
    gemm_k512<<<dim3(1, 8),       256>>>(nest, W + 512 * 512,  16, 1);
    gemm_k512<<<dim3(1, 8),       256>>>(seg,  W + 1024 * 512,  8, 2);

    combine_kernel<<<(BB * SS * H4 / 8) / 256, 256>>>(out);
}